// round 10
// baseline (speedup 1.0000x reference)
#include <cuda_runtime.h>
#include <cuda_fp16.h>
#include <cstdint>

#define B_     4096
#define N_IN   512
#define H1     1536
#define H2     1536
#define N_OUT  512
#define NODES  3584          // N_IN + H1 + H2
#define CAP    128           // bucket capacity per dst (Poisson(32), max ~66)
#define TBLOCKS 2048         // transpose blocks in fused setup kernel (16 x 128)
#define NSEG   128           // 4096 / 32 batch segments

typedef unsigned long long u64;

// ---------------- static device scratch (no allocations) ----------------
__device__ __align__(16) __half g_nvTh[NODES * B_];      // 29.4 MB
__device__ __align__(16) float  g_outT[N_OUT * B_];      //  8.4 MB
__device__ int  g_cnt[NODES];        // zero at load; re-zeroed by transpose_out
__device__ __align__(16) int2 g_bpack[NODES * CAP];      // (src, w-bits); slots >= cnt stay 0

// ---------------- packed f32x2 helpers ----------------
__device__ __forceinline__ u64 pack2(float x, float y) {
    u64 r; asm("mov.b64 %0, {%1, %2};" : "=l"(r) : "f"(x), "f"(y)); return r;
}
__device__ __forceinline__ float2 unpack2(u64 v) {
    float2 f; asm("mov.b64 {%0, %1}, %2;" : "=f"(f.x), "=f"(f.y) : "l"(v)); return f;
}
__device__ __forceinline__ void ffma2(u64& acc, u64 a, u64 b) {
    asm("fma.rn.f32x2 %0, %1, %2, %0;" : "+l"(acc) : "l"(a), "l"(b));
}
__device__ __forceinline__ u64 cvt2(uint32_t h2) {
    float2 f = __half22float2(*reinterpret_cast<const __half2*>(&h2));
    return pack2(f.x, f.y);
}
__device__ __forceinline__ uint32_t smem_u32(const void* p) {
    uint32_t a;
    asm("{ .reg .u64 t; cvta.to.shared.u64 t, %1; cvt.u32.u64 %0, t; }" : "=r"(a) : "l"(p));
    return a;
}
__device__ __forceinline__ void cp_async16(uint32_t dst, const void* src) {
    asm volatile("cp.async.cg.shared.global [%0], [%1], 16;"
                 :: "r"(dst), "l"(__cvta_generic_to_global(src)));
}
#define CP_COMMIT()  asm volatile("cp.async.commit_group;" ::: "memory")
#define CP_WAIT0()   asm volatile("cp.async.wait_group 0;" ::: "memory")

// ---------------- fused setup: transpose x -> fp16 nvT  +  bucket build ----
__global__ void setup_kernel(const float* __restrict__ x,
                             const int* __restrict__ src0, const int* __restrict__ dst0,
                             const float* __restrict__ w0, int E1,
                             const int* __restrict__ src1, const int* __restrict__ dst1,
                             const float* __restrict__ w1, int E2,
                             const int* __restrict__ src2, const int* __restrict__ dst2,
                             const float* __restrict__ w2, int E3) {
    const int tid = threadIdx.x;
    if (blockIdx.x < TBLOCKS) {
        __shared__ float tile[32][33];
        const int bx = (blockIdx.x & 15) * 32;   // node dim
        const int by = (blockIdx.x >> 4) * 32;   // batch dim
        const int tx = tid & 31, ty = tid >> 5;  // 32 x 8
#pragma unroll
        for (int i = 0; i < 32; i += 8)
            tile[ty + i][tx] = x[(size_t)(by + ty + i) * N_IN + bx + tx];
        __syncthreads();
#pragma unroll
        for (int i = 0; i < 32; i += 8)
            g_nvTh[(size_t)(bx + ty + i) * B_ + by + tx] = __float2half(tile[tx][ty + i]);
        return;
    }
    // ---- bucket part: 4 consecutive edges per thread ----
    int i0 = ((blockIdx.x - TBLOCKS) * 256 + tid) * 4;
    const int Etot = E1 + E2 + E3;
    if (i0 >= Etot) return;
    const int *sp, *dp; const float* wp; int dbase, j0;
    if (i0 < E1)           { sp = src0; dp = dst0; wp = w0; dbase = 0;       j0 = i0; }
    else if (i0 < E1 + E2) { sp = src1; dp = dst1; wp = w1; dbase = H1;      j0 = i0 - E1; }
    else                   { sp = src2; dp = dst2; wp = w2; dbase = H1 + H2; j0 = i0 - E1 - E2; }
    int4   s = *reinterpret_cast<const int4*>(sp + j0);
    int4   d = *reinterpret_cast<const int4*>(dp + j0);
    float4 w = *reinterpret_cast<const float4*>(wp + j0);
#pragma unroll
    for (int k = 0; k < 4; k++) {
        int sk = (&s.x)[k];
        int dk = dbase + (&d.x)[k];
        float wk = (&w.x)[k];
        int c = atomicAdd(&g_cnt[dk], 1);
        if (c < CAP)
            g_bpack[(size_t)dk * CAP + c] = make_int2(sk, __float_as_int(wk));
    }
}

// ---------------- output transpose + cnt reset for next call ----------------
__global__ void transpose_out_kernel(float* __restrict__ out) {
    if (blockIdx.x == 0 && blockIdx.y == 0) {
        for (int i = threadIdx.y * 32 + threadIdx.x; i < NODES; i += 256)
            g_cnt[i] = 0;
    }
    __shared__ float tile[32][33];
    const int bd = blockIdx.x * 32;
    const int bb = blockIdx.y * 32;
    const int tx = threadIdx.x, ty = threadIdx.y;
#pragma unroll
    for (int i = 0; i < 32; i += 8)
        tile[ty + i][tx] = g_outT[(size_t)(bd + ty + i) * B_ + bb + tx];
    __syncthreads();
#pragma unroll
    for (int i = 0; i < 32; i += 8)
        out[(size_t)(bb + ty + i) * N_OUT + bd + tx] = tile[tx][ty + i];
}

// ---------------- SMEM-tiled sparse level kernel ----------------
// Grid = 128 CTAs (one per 32-col batch segment), 512 threads.
// Phase A: load 64B segment of every source row into SMEM (row r at r*64,
//          chunk c at +c*16 — i.e. flat i*16 for i = r*4+c).
// Phase B: 4 lanes per dst (tsub = chunk), 8 cols (16B) per lane, all HOUT
//          dsts of the level; fp32 accumulate via f32x2; relu; store.
// Buckets processed in uniform 4-edge blocks; zero-pad slots contribute 0.
template <int ROWS, int HOUT, int CBASE, bool F32OUT>
__global__ void __launch_bounds__(512)
level_tiled_kernel(__half* __restrict__ outh, float* __restrict__ outf) {
    extern __shared__ __align__(16) char smem[];
    const int seg = blockIdx.x;
    const int c0  = seg * 32;
    const int t   = threadIdx.x;
    const uint32_t sb = smem_u32(smem);

    // ---- Phase A: stage source-row segments ----
#pragma unroll 4
    for (int i = t; i < ROWS * 4; i += 512) {
        int r = i >> 2, c = i & 3;
        cp_async16(sb + (uint32_t)i * 16, g_nvTh + (size_t)r * B_ + c0 + c * 8);
    }
    CP_COMMIT();
    CP_WAIT0();
    __syncthreads();

    // ---- Phase B ----
    const int dgrp = t >> 2;          // 0..127
    const int tsub = t & 3;           // chunk within row
    const uint32_t lane_off = (uint32_t)tsub * 16;

#pragma unroll 1
    for (int d0 = 0; d0 < HOUT; d0 += 128) {
        const int d = d0 + dgrp;
        int cnt = g_cnt[CBASE + d];
        if (cnt > CAP) cnt = CAP;
        const int cntUp = (cnt + 3) & ~3;
        const int2* bp = g_bpack + (size_t)(CBASE + d) * CAP;

        u64 acc[4] = {0, 0, 0, 0};
        for (int e = 0; e < cntUp; e += 4) {
            int4 m0 = *reinterpret_cast<const int4*>(bp + e);       // s0,w0,s1,w1
            int4 m1 = *reinterpret_cast<const int4*>(bp + e + 2);   // s2,w2,s3,w3
            uint4 v0, v1, v2, v3;
            asm volatile("ld.shared.v4.u32 {%0,%1,%2,%3}, [%4];"
                         : "=r"(v0.x), "=r"(v0.y), "=r"(v0.z), "=r"(v0.w)
                         : "r"(sb + (uint32_t)m0.x * 64 + lane_off));
            asm volatile("ld.shared.v4.u32 {%0,%1,%2,%3}, [%4];"
                         : "=r"(v1.x), "=r"(v1.y), "=r"(v1.z), "=r"(v1.w)
                         : "r"(sb + (uint32_t)m0.z * 64 + lane_off));
            asm volatile("ld.shared.v4.u32 {%0,%1,%2,%3}, [%4];"
                         : "=r"(v2.x), "=r"(v2.y), "=r"(v2.z), "=r"(v2.w)
                         : "r"(sb + (uint32_t)m1.x * 64 + lane_off));
            asm volatile("ld.shared.v4.u32 {%0,%1,%2,%3}, [%4];"
                         : "=r"(v3.x), "=r"(v3.y), "=r"(v3.z), "=r"(v3.w)
                         : "r"(sb + (uint32_t)m1.z * 64 + lane_off));
            u64 W0 = pack2(__int_as_float(m0.y), __int_as_float(m0.y));
            u64 W1 = pack2(__int_as_float(m0.w), __int_as_float(m0.w));
            u64 W2 = pack2(__int_as_float(m1.y), __int_as_float(m1.y));
            u64 W3 = pack2(__int_as_float(m1.w), __int_as_float(m1.w));
            ffma2(acc[0], W0, cvt2(v0.x)); ffma2(acc[1], W0, cvt2(v0.y));
            ffma2(acc[2], W0, cvt2(v0.z)); ffma2(acc[3], W0, cvt2(v0.w));
            ffma2(acc[0], W1, cvt2(v1.x)); ffma2(acc[1], W1, cvt2(v1.y));
            ffma2(acc[2], W1, cvt2(v1.z)); ffma2(acc[3], W1, cvt2(v1.w));
            ffma2(acc[0], W2, cvt2(v2.x)); ffma2(acc[1], W2, cvt2(v2.y));
            ffma2(acc[2], W2, cvt2(v2.z)); ffma2(acc[3], W2, cvt2(v2.w));
            ffma2(acc[0], W3, cvt2(v3.x)); ffma2(acc[1], W3, cvt2(v3.y));
            ffma2(acc[2], W3, cvt2(v3.z)); ffma2(acc[3], W3, cvt2(v3.w));
        }

        float r[8];
#pragma unroll
        for (int j = 0; j < 4; j++) {
            float2 f = unpack2(acc[j]);
            r[2 * j]     = fmaxf(f.x, 0.f);
            r[2 * j + 1] = fmaxf(f.y, 0.f);
        }
        if (F32OUT) {
            float* p = outf + (size_t)d * B_ + c0 + tsub * 8;
            *reinterpret_cast<float4*>(p)     = make_float4(r[0], r[1], r[2], r[3]);
            *reinterpret_cast<float4*>(p + 4) = make_float4(r[4], r[5], r[6], r[7]);
        } else {
            uint4 o; __half2 h;
            h = __floats2half2_rn(r[0], r[1]); o.x = *reinterpret_cast<uint32_t*>(&h);
            h = __floats2half2_rn(r[2], r[3]); o.y = *reinterpret_cast<uint32_t*>(&h);
            h = __floats2half2_rn(r[4], r[5]); o.z = *reinterpret_cast<uint32_t*>(&h);
            h = __floats2half2_rn(r[6], r[7]); o.w = *reinterpret_cast<uint32_t*>(&h);
            *reinterpret_cast<uint4*>(outh + (size_t)d * B_ + c0 + tsub * 8) = o;
        }
    }
}

// ---------------- launch ----------------
extern "C" void kernel_launch(void* const* d_in, const int* in_sizes, int n_in,
                              void* d_out, int out_size) {
    const float* x    = (const float*)d_in[0];
    const int*   src0 = (const int*)  d_in[1];
    const int*   dst0 = (const int*)  d_in[2];
    const float* w0   = (const float*)d_in[3];
    const int*   src1 = (const int*)  d_in[4];
    const int*   dst1 = (const int*)  d_in[5];
    const float* w1   = (const float*)d_in[6];
    const int*   src2 = (const int*)  d_in[7];
    const int*   dst2 = (const int*)  d_in[8];
    const float* w2   = (const float*)d_in[9];
    float* out = (float*)d_out;

    __half* pnvTh; cudaGetSymbolAddress((void**)&pnvTh, g_nvTh);
    float*  poutT; cudaGetSymbolAddress((void**)&poutT, g_outT);

    const int E1 = in_sizes[1], E2 = in_sizes[4], E3 = in_sizes[7];
    const int Etot = E1 + E2 + E3;

    constexpr int SM1 = 512  * 64;   //  32 KB
    constexpr int SM2 = 2048 * 64;   // 128 KB
    constexpr int SM3 = 3584 * 64;   // 224 KB
    cudaFuncSetAttribute((const void*)level_tiled_kernel<512,  H1,    0,       false>,
                         cudaFuncAttributeMaxDynamicSharedMemorySize, SM1);
    cudaFuncSetAttribute((const void*)level_tiled_kernel<2048, H2,    H1,      false>,
                         cudaFuncAttributeMaxDynamicSharedMemorySize, SM2);
    cudaFuncSetAttribute((const void*)level_tiled_kernel<3584, N_OUT, H1 + H2, true>,
                         cudaFuncAttributeMaxDynamicSharedMemorySize, SM3);

    // 1) fused setup: transpose x (fp32->fp16) + build edge buckets
    {
        int bucketBlocks = (Etot + 1023) / 1024;
        setup_kernel<<<TBLOCKS + bucketBlocks, 256>>>(
            x, src0, dst0, w0, E1, src1, dst1, w1, E2, src2, dst2, w2, E3);
    }

    // 2) SMEM-tiled sparse levels (one CTA per 32-col batch segment)
    level_tiled_kernel<512,  H1,    0,       false><<<NSEG, 512, SM1>>>(
        pnvTh + (size_t)N_IN * B_, nullptr);
    level_tiled_kernel<2048, H2,    H1,      false><<<NSEG, 512, SM2>>>(
        pnvTh + (size_t)(N_IN + H1) * B_, nullptr);
    level_tiled_kernel<3584, N_OUT, H1 + H2, true ><<<NSEG, 512, SM3>>>(
        nullptr, poutT);

    // 3) transpose result to [B, N_OUT] (+ reset g_cnt for next call)
    transpose_out_kernel<<<dim3(N_OUT / 32, B_ / 32), dim3(32, 8)>>>(out);
}